// round 3
// baseline (speedup 1.0000x reference)
#include <cuda_runtime.h>

#define N_SRC 65536
#define N_DST 8192
#define MAXN  32
#define H     128

// ---------------- scratch (static device globals; no allocs allowed) ----------------
__device__ __align__(16) float g_feat_sim[N_SRC * H];
__device__ __align__(16) float g_feat_cor[N_SRC * H];
__device__ __align__(16) float g_rst_sim[N_DST * H];
__device__ __align__(16) float g_rst_cor[N_DST * H];
__device__ __align__(16) float g_sim[N_DST * H];
__device__ __align__(16) float g_cor[N_DST * H];
__device__ __align__(16) float g_P[N_DST * H];     // cor @ W_cor2sim
__device__ __align__(16) float g_S[N_DST * H];     // sim @ W_sim2cor
__device__ __align__(16) float g_z1sim[N_DST * H];
__device__ __align__(16) float g_z1cor[N_DST * H];
__device__ __align__(16) float g_T1[N_DST * H];    // z1cor @ W_cor2sim
__device__ __align__(16) float g_T2[N_DST * H];    // z1sim @ W_sim2cor

// ---------------- kernel 1: feat = [emb0[x0] | emb1[x1]] @ W_in + b ----------------
// 32 rows per CTA, 128 threads: thread j computes output column j for all 32 rows.
__global__ __launch_bounds__(128) void feat_kernel(
    const int* __restrict__ x,
    const float* __restrict__ emb0, const float* __restrict__ emb1,
    const float* __restrict__ W, const float* __restrict__ b,
    float* __restrict__ out)
{
    __shared__ float xbuf[32][H];
    const int base = blockIdx.x * 32;
    const int tid = threadIdx.x;

    // gather: row r, channel h.  h<32 -> emb0[x0], else emb1[x1]
    for (int idx = tid; idx < 32 * H; idx += 128) {
        const int r = idx >> 7, h = idx & 127;
        const int row = base + r;
        float v;
        if (h < 32) v = emb0[x[row * 2 + 0] * 32 + h];
        else        v = emb1[x[row * 2 + 1] * 96 + (h - 32)];
        xbuf[r][h] = v;
    }
    __syncthreads();

    const int j = tid;
    float acc[32];
#pragma unroll
    for (int r = 0; r < 32; r++) acc[r] = 0.f;

#pragma unroll 2
    for (int h4 = 0; h4 < 32; ++h4) {
        const float w0 = W[(h4 * 4 + 0) * H + j];
        const float w1 = W[(h4 * 4 + 1) * H + j];
        const float w2 = W[(h4 * 4 + 2) * H + j];
        const float w3 = W[(h4 * 4 + 3) * H + j];
#pragma unroll
        for (int r = 0; r < 32; r++) {
            const float4 xv = *(const float4*)&xbuf[r][h4 * 4];
            acc[r] += xv.x * w0 + xv.y * w1 + xv.z * w2 + xv.w * w3;
        }
    }
    const float bj = b ? b[j] : 0.f;
#pragma unroll
    for (int r = 0; r < 32; r++) out[(base + r) * H + j] = acc[r] + bj;
}

// ---------------- kernel 2: generic  Y = A @ W (+ b),  A is n x 128 ----------------
__global__ __launch_bounds__(128) void gemm_kernel(
    const float* __restrict__ A, const float* __restrict__ W,
    const float* __restrict__ b, float* __restrict__ out)
{
    __shared__ float xbuf[32][H];
    const int base = blockIdx.x * 32;
    const int tid = threadIdx.x;

    // load 32 rows (coalesced float4)
    for (int idx = tid; idx < 32 * H / 4; idx += 128)
        ((float4*)xbuf)[idx] = ((const float4*)A)[base * (H / 4) + idx];
    __syncthreads();

    const int j = tid;
    float acc[32];
#pragma unroll
    for (int r = 0; r < 32; r++) acc[r] = 0.f;

#pragma unroll 2
    for (int h4 = 0; h4 < 32; ++h4) {
        const float w0 = W[(h4 * 4 + 0) * H + j];
        const float w1 = W[(h4 * 4 + 1) * H + j];
        const float w2 = W[(h4 * 4 + 2) * H + j];
        const float w3 = W[(h4 * 4 + 3) * H + j];
#pragma unroll
        for (int r = 0; r < 32; r++) {
            const float4 xv = *(const float4*)&xbuf[r][h4 * 4];
            acc[r] += xv.x * w0 + xv.y * w1 + xv.z * w2 + xv.w * w3;
        }
    }
    const float bj = b ? b[j] : 0.f;
#pragma unroll
    for (int r = 0; r < 32; r++) out[(base + r) * H + j] = acc[r] + bj;
}

// ---------------- kernel 3: co-attention pool, collapsed under the mean ----------------
// One CTA (128 threads) per dst node.
// Needed outputs (after summing pooled over m and the 3-way channel fold):
//   rowmax/rowsum over k of L[m][:]  (for AC)
//   colmax/colsum over m of L[:][k]  (for AS)
//   w[m] = sum_k AS[k][m],  v[k] = sum_m w[m]*AC[m][k]
//   SumQ[h]   = sum_m Q[m][h]
//   SumDw[h]  = sum_m w[m]*D[m][h]
//   SumCQ[h]  = sum_k v[k]*Q[k][h]
//   O = [SumQ | SumDw | SumCQ]  (384);  result[h] = (O[3h]+O[3h+1]+O[3h+2])/96
//   rst[h] = feat[node][h] + result[h]
__global__ __launch_bounds__(128) void attn_kernel(
    const float* __restrict__ feat,
    const int* __restrict__ idxD, const int* __restrict__ idxQ,
    float* __restrict__ rst)
{
    __shared__ float Ds[32][H];      // D rows (row-major)
    __shared__ float Qt[H][33];      // Q transposed, padded
    __shared__ float Ls[32][33];
    __shared__ float rowmax[32], rowsum[32], colmax[32], colsum[32];
    __shared__ float wv[32], vv[32];
    __shared__ float O[3 * H];

    const int node = blockIdx.x;
    const int tid = threadIdx.x;
    const int lane = tid & 31, wid = tid >> 5;

    // gather D (row-major) and Q (transposed)
    for (int r = wid; r < 32; r += 4) {
        const int idd = idxD[node * 32 + r];
        const float4 dv = ((const float4*)feat)[idd * (H / 4) + lane];
        *(float4*)&Ds[r][lane * 4] = dv;
        const int idq = idxQ[node * 32 + r];
        const float4 qv = ((const float4*)feat)[idq * (H / 4) + lane];
        Qt[lane * 4 + 0][r] = qv.x;
        Qt[lane * 4 + 1][r] = qv.y;
        Qt[lane * 4 + 2][r] = qv.z;
        Qt[lane * 4 + 3][r] = qv.w;
    }
    __syncthreads();

    // L[m][k] = sum_h D[m][h]*Q[k][h]; warp wid owns m in [wid*8, wid*8+8), lane = k
    {
        float acc[8];
#pragma unroll
        for (int i = 0; i < 8; i++) acc[i] = 0.f;
        const int m0 = wid * 8;
        for (int h4 = 0; h4 < 32; ++h4) {
            const float q0 = Qt[h4 * 4 + 0][lane];
            const float q1 = Qt[h4 * 4 + 1][lane];
            const float q2 = Qt[h4 * 4 + 2][lane];
            const float q3 = Qt[h4 * 4 + 3][lane];
#pragma unroll
            for (int i = 0; i < 8; i++) {
                const float4 d = *(const float4*)&Ds[m0 + i][h4 * 4];
                acc[i] += d.x * q0 + d.y * q1 + d.z * q2 + d.w * q3;
            }
        }
#pragma unroll
        for (int i = 0; i < 8; i++) Ls[m0 + i][lane] = acc[i];
    }
    __syncthreads();

    // softmax stats
    if (tid < 32) {
        const int m = tid;
        float mx = -1e30f;
        for (int k = 0; k < 32; k++) mx = fmaxf(mx, Ls[m][k]);
        float s = 0.f;
        for (int k = 0; k < 32; k++) s += __expf(Ls[m][k] - mx);
        rowmax[m] = mx; rowsum[m] = s;
    } else if (tid < 64) {
        const int k = tid - 32;
        float mx = -1e30f;
        for (int m = 0; m < 32; m++) mx = fmaxf(mx, Ls[m][k]);
        float s = 0.f;
        for (int m = 0; m < 32; m++) s += __expf(Ls[m][k] - mx);
        colmax[k] = mx; colsum[k] = s;
    }
    __syncthreads();

    if (tid < 32) {                 // w[m] = sum_k AS[k][m]
        const int m = tid;
        float s = 0.f;
        for (int k = 0; k < 32; k++)
            s += __expf(Ls[m][k] - colmax[k]) / colsum[k];
        wv[m] = s;
    }
    __syncthreads();

    if (tid < 32) {                 // v[k] = sum_m w[m]*AC[m][k]
        const int k = tid;
        float s = 0.f;
        for (int m = 0; m < 32; m++)
            s += (wv[m] / rowsum[m]) * __expf(Ls[m][k] - rowmax[m]);
        vv[k] = s;
    }
    __syncthreads();

    // channel reductions
    {
        const int h = tid;
        float sq = 0.f, sdw = 0.f, scq = 0.f;
        for (int m = 0; m < 32; m++) {
            const float qv = Qt[h][m];
            sq  += qv;
            scq += vv[m] * qv;
            sdw += wv[m] * Ds[m][h];
        }
        O[h]         = sq;
        O[H + h]     = sdw;
        O[2 * H + h] = scq;
    }
    __syncthreads();
    {
        const int h = tid;
        const float r = (O[3 * h] + O[3 * h + 1] + O[3 * h + 2]) * (1.f / 96.f);
        rst[node * H + h] = feat[node * H + h] + r;   // + h_self
    }
}

// ---------------- elementwise combines ----------------
__global__ void combine2_kernel(float* __restrict__ out,
                                const float* __restrict__ a, const float* __restrict__ b,
                                float pa, float pb, int n)
{
    const int i = blockIdx.x * blockDim.x + threadIdx.x;
    if (i < n) out[i] = pa * a[i] + pb * b[i];
}

__global__ void combine3_kernel(float* __restrict__ out,
                                const float* __restrict__ a, const float* __restrict__ b,
                                const float* __restrict__ c,
                                float pa, float pb, float pc, int n)
{
    const int i = blockIdx.x * blockDim.x + threadIdx.x;
    if (i < n) out[i] = pa * a[i] + pb * b[i] + pc * c[i];
}

// ---------------- launch ----------------
extern "C" void kernel_launch(void* const* d_in, const int* in_sizes, int n_in,
                              void* d_out, int out_size)
{
    const int*   x         = (const int*)d_in[0];
    const int*   neigh_sim = (const int*)d_in[1];
    const int*   neigh_cor = (const int*)d_in[2];
    const float* emb0_sim  = (const float*)d_in[3];
    const float* emb1_sim  = (const float*)d_in[4];
    const float* emb0_cor  = (const float*)d_in[5];
    const float* emb1_cor  = (const float*)d_in[6];
    const float* W_in_sim  = (const float*)d_in[7];
    const float* b_in_sim  = (const float*)d_in[8];
    const float* W_in_cor  = (const float*)d_in[9];
    const float* b_in_cor  = (const float*)d_in[10];
    const float* W_out_sim = (const float*)d_in[11];
    const float* b_out_sim = (const float*)d_in[12];
    const float* W_out_cor = (const float*)d_in[13];
    const float* b_out_cor = (const float*)d_in[14];
    const float* W_sim2cor = (const float*)d_in[15];
    const float* W_cor2sim = (const float*)d_in[16];

    float *feat_sim, *feat_cor, *rst_sim, *rst_cor, *simB, *corB;
    float *P, *S, *z1sim, *z1cor, *T1, *T2;
    cudaGetSymbolAddress((void**)&feat_sim, g_feat_sim);
    cudaGetSymbolAddress((void**)&feat_cor, g_feat_cor);
    cudaGetSymbolAddress((void**)&rst_sim,  g_rst_sim);
    cudaGetSymbolAddress((void**)&rst_cor,  g_rst_cor);
    cudaGetSymbolAddress((void**)&simB,     g_sim);
    cudaGetSymbolAddress((void**)&corB,     g_cor);
    cudaGetSymbolAddress((void**)&P,        g_P);
    cudaGetSymbolAddress((void**)&S,        g_S);
    cudaGetSymbolAddress((void**)&z1sim,    g_z1sim);
    cudaGetSymbolAddress((void**)&z1cor,    g_z1cor);
    cudaGetSymbolAddress((void**)&T1,       g_T1);
    cudaGetSymbolAddress((void**)&T2,       g_T2);

    float* out = (float*)d_out;
    const int n = N_DST * H;

    // stage 1: per-mode features
    feat_kernel<<<N_SRC / 32, 128>>>(x, emb0_sim, emb1_sim, W_in_sim, b_in_sim, feat_sim);
    feat_kernel<<<N_SRC / 32, 128>>>(x, emb0_cor, emb1_cor, W_in_cor, b_in_cor, feat_cor);

    // stage 2: co-attention pooling (+ h_self)
    // mode 'sim': D = nf_cor, Q = nf_sim ; mode 'cor': D = nf_sim, Q = nf_cor
    attn_kernel<<<N_DST, 128>>>(feat_sim, neigh_cor, neigh_sim, rst_sim);
    attn_kernel<<<N_DST, 128>>>(feat_cor, neigh_sim, neigh_cor, rst_cor);

    // stage 3: output projection
    gemm_kernel<<<N_DST / 32, 128>>>(rst_sim, W_out_sim, b_out_sim, simB);
    gemm_kernel<<<N_DST / 32, 128>>>(rst_cor, W_out_cor, b_out_cor, corB);

    // stage 4: mixing
    gemm_kernel<<<N_DST / 32, 128>>>(corB, W_cor2sim, nullptr, P);
    gemm_kernel<<<N_DST / 32, 128>>>(simB, W_sim2cor, nullptr, S);
    combine2_kernel<<<n / 256, 256>>>(z1sim, simB, P, 0.5f, 0.5f, n);
    combine2_kernel<<<n / 256, 256>>>(z1cor, corB, S, 0.5f, 0.5f, n);
    gemm_kernel<<<N_DST / 32, 128>>>(z1cor, W_cor2sim, nullptr, T1);
    gemm_kernel<<<N_DST / 32, 128>>>(z1sim, W_sim2cor, nullptr, T2);
    combine3_kernel<<<n / 256, 256>>>(out,     simB, P, T1, 0.34f, 0.33f, 0.33f, n);
    combine3_kernel<<<n / 256, 256>>>(out + n, corB, S, T2, 0.34f, 0.33f, 0.33f, n);
}

// round 4
// speedup vs baseline: 1.2628x; 1.2628x over previous
#include <cuda_runtime.h>

#define N_SRC 65536
#define N_DST 8192
#define MAXN  32
#define H     128

// ---------------- scratch ----------------
__device__ __align__(16) float g_feat_sim[N_SRC * H];
__device__ __align__(16) float g_feat_cor[N_SRC * H];
__device__ __align__(16) float g_rst_sim[N_DST * H];
__device__ __align__(16) float g_rst_cor[N_DST * H];
__device__ __align__(16) float g_sim[N_DST * H];
__device__ __align__(16) float g_cor[N_DST * H];
__device__ __align__(16) float g_P[N_DST * H];
__device__ __align__(16) float g_S[N_DST * H];
__device__ __align__(16) float g_z1sim[N_DST * H];
__device__ __align__(16) float g_z1cor[N_DST * H];
__device__ __align__(16) float g_T1[N_DST * H];
__device__ __align__(16) float g_T2[N_DST * H];

// ---------------- feat: both modes in one launch ----------------
// 32 rows per CTA, 128 threads: thread j computes output column j for 32 rows.
__global__ __launch_bounds__(128) void feat_kernel(
    const int* __restrict__ x,
    const float* __restrict__ e0s, const float* __restrict__ e1s,
    const float* __restrict__ Ws,  const float* __restrict__ bs, float* __restrict__ outs,
    const float* __restrict__ e0c, const float* __restrict__ e1c,
    const float* __restrict__ Wc,  const float* __restrict__ bc, float* __restrict__ outc)
{
    __shared__ float xbuf[32][H];
    const bool is_sim = blockIdx.x < (N_SRC / 32);
    const int  blk    = is_sim ? blockIdx.x : blockIdx.x - (N_SRC / 32);
    const float* emb0 = is_sim ? e0s : e0c;
    const float* emb1 = is_sim ? e1s : e1c;
    const float* W    = is_sim ? Ws  : Wc;
    const float* b    = is_sim ? bs  : bc;
    float*       out  = is_sim ? outs : outc;

    const int base = blk * 32;
    const int tid = threadIdx.x;

    for (int idx = tid; idx < 32 * H; idx += 128) {
        const int r = idx >> 7, h = idx & 127;
        const int row = base + r;
        float v;
        if (h < 32) v = emb0[x[row * 2 + 0] * 32 + h];
        else        v = emb1[x[row * 2 + 1] * 96 + (h - 32)];
        xbuf[r][h] = v;
    }
    __syncthreads();

    const int j = tid;
    float acc[32];
#pragma unroll
    for (int r = 0; r < 32; r++) acc[r] = 0.f;

#pragma unroll 2
    for (int h4 = 0; h4 < 32; ++h4) {
        const float w0 = W[(h4 * 4 + 0) * H + j];
        const float w1 = W[(h4 * 4 + 1) * H + j];
        const float w2 = W[(h4 * 4 + 2) * H + j];
        const float w3 = W[(h4 * 4 + 3) * H + j];
#pragma unroll
        for (int r = 0; r < 32; r++) {
            const float4 xv = *(const float4*)&xbuf[r][h4 * 4];
            acc[r] += xv.x * w0 + xv.y * w1 + xv.z * w2 + xv.w * w3;
        }
    }
    const float bj = b[j];
#pragma unroll
    for (int r = 0; r < 32; r++) out[(base + r) * H + j] = acc[r] + bj;
}

// ---------------- paired GEMM: two independent Y = A @ W (+b) in one launch ----------------
__global__ __launch_bounds__(128) void gemm_pair_kernel(
    const float* __restrict__ A0, const float* __restrict__ W0,
    const float* __restrict__ b0, float* __restrict__ out0,
    const float* __restrict__ A1, const float* __restrict__ W1,
    const float* __restrict__ b1, float* __restrict__ out1)
{
    __shared__ float xbuf[32][H];
    const bool first = blockIdx.x < (N_DST / 32);
    const int  blk   = first ? blockIdx.x : blockIdx.x - (N_DST / 32);
    const float* A = first ? A0 : A1;
    const float* W = first ? W0 : W1;
    const float* b = first ? b0 : b1;
    float*     out = first ? out0 : out1;

    const int base = blk * 32;
    const int tid = threadIdx.x;

    for (int idx = tid; idx < 32 * H / 4; idx += 128)
        ((float4*)xbuf)[idx] = ((const float4*)A)[base * (H / 4) + idx];
    __syncthreads();

    const int j = tid;
    float acc[32];
#pragma unroll
    for (int r = 0; r < 32; r++) acc[r] = 0.f;

#pragma unroll 2
    for (int h4 = 0; h4 < 32; ++h4) {
        const float w0 = W[(h4 * 4 + 0) * H + j];
        const float w1 = W[(h4 * 4 + 1) * H + j];
        const float w2 = W[(h4 * 4 + 2) * H + j];
        const float w3 = W[(h4 * 4 + 3) * H + j];
#pragma unroll
        for (int r = 0; r < 32; r++) {
            const float4 xv = *(const float4*)&xbuf[r][h4 * 4];
            acc[r] += xv.x * w0 + xv.y * w1 + xv.z * w2 + xv.w * w3;
        }
    }
    const float bj = b ? b[j] : 0.f;
#pragma unroll
    for (int r = 0; r < 32; r++) out[(base + r) * H + j] = acc[r] + bj;
}

// ---------------- co-attention pool (collapsed under the mean), both modes ----------------
// 256 threads per node. Warp w owns k-block [4w, 4w+4), lane = m.
// E = exp(L) computed ONCE and kept in registers; all softmax stats via
// warp butterflies + 8-way partial combines. No Ls array in smem.
__global__ __launch_bounds__(256, 5) void attn_kernel(
    const float* __restrict__ feat_sim, const float* __restrict__ feat_cor,
    const int* __restrict__ neigh_sim, const int* __restrict__ neigh_cor,
    float* __restrict__ rst_sim, float* __restrict__ rst_cor)
{
    __shared__ float Ds[32][132];   // row-major, 132-pad: per-lane float4 reads conflict-free
    __shared__ float Qs[32][132];
    __shared__ float rowpart[8][32];
    __shared__ float wvpart[8][32];
    __shared__ float invcol[32];
    __shared__ float invrow[32];
    __shared__ float wv[32];
    __shared__ float vv[32];
    __shared__ float coef[32];
    __shared__ float O[3 * H];

    const bool is_sim = blockIdx.x < N_DST;
    const int  node   = is_sim ? blockIdx.x : (blockIdx.x - N_DST);
    const float* feat = is_sim ? feat_sim : feat_cor;
    // sim: D = nf_cor, Q = nf_sim ; cor: D = nf_sim, Q = nf_cor
    const int* idxD = is_sim ? neigh_cor : neigh_sim;
    const int* idxQ = is_sim ? neigh_sim : neigh_cor;
    float*     rst  = is_sim ? rst_sim : rst_cor;

    const int tid = threadIdx.x;
    const int lane = tid & 31;
    const int w = tid >> 5;

    // gather: warp w loads D rows and Q rows [4w, 4w+4), all coalesced float4
#pragma unroll
    for (int i = 0; i < 4; i++) {
        const int r = w * 4 + i;
        const int id = idxD[node * 32 + r];
        ((float4*)&Ds[r][0])[lane] = ((const float4*)feat)[id * 32 + lane];
        const int iq = idxQ[node * 32 + r];
        ((float4*)&Qs[r][0])[lane] = ((const float4*)feat)[iq * 32 + lane];
    }
    __syncthreads();

    // L[m][k] + exp, k in [4w,4w+4), m = lane
    float e0, e1, e2, e3;
    {
        float a0 = 0.f, a1 = 0.f, a2 = 0.f, a3 = 0.f;
        const int k0 = w * 4;
        const float* drow = &Ds[lane][0];
        const float* q0r = &Qs[k0 + 0][0];
        const float* q1r = &Qs[k0 + 1][0];
        const float* q2r = &Qs[k0 + 2][0];
        const float* q3r = &Qs[k0 + 3][0];
#pragma unroll
        for (int h4 = 0; h4 < 32; ++h4) {
            const float4 d  = ((const float4*)drow)[h4];
            const float4 q0 = ((const float4*)q0r)[h4];
            const float4 q1 = ((const float4*)q1r)[h4];
            const float4 q2 = ((const float4*)q2r)[h4];
            const float4 q3 = ((const float4*)q3r)[h4];
            a0 += d.x * q0.x + d.y * q0.y + d.z * q0.z + d.w * q0.w;
            a1 += d.x * q1.x + d.y * q1.y + d.z * q1.z + d.w * q1.w;
            a2 += d.x * q2.x + d.y * q2.y + d.z * q2.z + d.w * q2.w;
            a3 += d.x * q3.x + d.y * q3.y + d.z * q3.z + d.w * q3.w;
        }
        e0 = __expf(a0); e1 = __expf(a1); e2 = __expf(a2); e3 = __expf(a3);

        // row partial (sum over my 4 k's) for rowsum[m]
        rowpart[w][lane] = e0 + e1 + e2 + e3;

        // colsum[k] complete within this warp (sum over m = lanes)
        float s0 = e0, s1 = e1, s2 = e2, s3 = e3;
#pragma unroll
        for (int off = 16; off; off >>= 1) {
            s0 += __shfl_xor_sync(0xffffffffu, s0, off);
            s1 += __shfl_xor_sync(0xffffffffu, s1, off);
            s2 += __shfl_xor_sync(0xffffffffu, s2, off);
            s3 += __shfl_xor_sync(0xffffffffu, s3, off);
        }
        if (lane == 0) {
            invcol[k0 + 0] = __frcp_rn(s0);
            invcol[k0 + 1] = __frcp_rn(s1);
            invcol[k0 + 2] = __frcp_rn(s2);
            invcol[k0 + 3] = __frcp_rn(s3);
        }
    }
    __syncthreads();

    // rowsum -> invrow
    if (tid < 32) {
        float s = 0.f;
#pragma unroll
        for (int i = 0; i < 8; i++) s += rowpart[i][tid];
        invrow[tid] = __frcp_rn(s);
    }
    __syncthreads();

    // wv[m] = sum_k E[m][k] * invcol[k]  (partials per warp over its 4 k's)
    {
        const int k0 = w * 4;
        wvpart[w][lane] = e0 * invcol[k0] + e1 * invcol[k0 + 1]
                        + e2 * invcol[k0 + 2] + e3 * invcol[k0 + 3];
    }
    __syncthreads();
    if (tid < 32) {
        float s = 0.f;
#pragma unroll
        for (int i = 0; i < 8; i++) s += wvpart[i][tid];
        wv[tid]   = s;
        coef[tid] = s * invrow[tid];
    }
    __syncthreads();

    // vv[k] = sum_m coef[m] * E[m][k]  (complete within warp via butterfly)
    {
        const float c = coef[lane];
        float s0 = c * e0, s1 = c * e1, s2 = c * e2, s3 = c * e3;
#pragma unroll
        for (int off = 16; off; off >>= 1) {
            s0 += __shfl_xor_sync(0xffffffffu, s0, off);
            s1 += __shfl_xor_sync(0xffffffffu, s1, off);
            s2 += __shfl_xor_sync(0xffffffffu, s2, off);
            s3 += __shfl_xor_sync(0xffffffffu, s3, off);
        }
        if (lane == 0) {
            const int k0 = w * 4;
            vv[k0 + 0] = s0; vv[k0 + 1] = s1; vv[k0 + 2] = s2; vv[k0 + 3] = s3;
        }
    }
    __syncthreads();

    // channel reductions: threads 0-127 -> sq/scq over Q, 128-255 -> sdw over D
    if (tid < 128) {
        const int h = tid;
        float sq = 0.f, scq = 0.f;
#pragma unroll
        for (int m = 0; m < 32; m++) {
            const float q = Qs[m][h];
            sq  += q;
            scq += vv[m] * q;
        }
        O[h]           = sq;
        O[2 * H + h]   = scq;
    } else {
        const int h = tid - 128;
        float sdw = 0.f;
#pragma unroll
        for (int m = 0; m < 32; m++) sdw += wv[m] * Ds[m][h];
        O[H + h] = sdw;
    }
    __syncthreads();

    if (tid < 128) {
        const int h = tid;
        const float r = (O[3 * h] + O[3 * h + 1] + O[3 * h + 2]) * (1.f / 96.f);
        rst[node * H + h] = feat[node * H + h] + r;   // + h_self
    }
}

// ---------------- combines (both modes fused) ----------------
__global__ void combine_z1_kernel(float* __restrict__ z1sim, float* __restrict__ z1cor,
                                  const float* __restrict__ simB, const float* __restrict__ corB,
                                  const float* __restrict__ P, const float* __restrict__ S, int n)
{
    const int i = blockIdx.x * blockDim.x + threadIdx.x;
    if (i < n) {
        z1sim[i] = 0.5f * simB[i] + 0.5f * P[i];
        z1cor[i] = 0.5f * corB[i] + 0.5f * S[i];
    }
}

__global__ void combine_final_kernel(float* __restrict__ out,
                                     const float* __restrict__ simB, const float* __restrict__ corB,
                                     const float* __restrict__ P,  const float* __restrict__ S,
                                     const float* __restrict__ T1, const float* __restrict__ T2, int n)
{
    const int i = blockIdx.x * blockDim.x + threadIdx.x;
    if (i < n) {
        out[i]     = 0.34f * simB[i] + 0.33f * P[i] + 0.33f * T1[i];
        out[n + i] = 0.34f * corB[i] + 0.33f * S[i] + 0.33f * T2[i];
    }
}

// ---------------- launch ----------------
extern "C" void kernel_launch(void* const* d_in, const int* in_sizes, int n_in,
                              void* d_out, int out_size)
{
    const int*   x         = (const int*)d_in[0];
    const int*   neigh_sim = (const int*)d_in[1];
    const int*   neigh_cor = (const int*)d_in[2];
    const float* emb0_sim  = (const float*)d_in[3];
    const float* emb1_sim  = (const float*)d_in[4];
    const float* emb0_cor  = (const float*)d_in[5];
    const float* emb1_cor  = (const float*)d_in[6];
    const float* W_in_sim  = (const float*)d_in[7];
    const float* b_in_sim  = (const float*)d_in[8];
    const float* W_in_cor  = (const float*)d_in[9];
    const float* b_in_cor  = (const float*)d_in[10];
    const float* W_out_sim = (const float*)d_in[11];
    const float* b_out_sim = (const float*)d_in[12];
    const float* W_out_cor = (const float*)d_in[13];
    const float* b_out_cor = (const float*)d_in[14];
    const float* W_sim2cor = (const float*)d_in[15];
    const float* W_cor2sim = (const float*)d_in[16];

    float *feat_sim, *feat_cor, *rst_sim, *rst_cor, *simB, *corB;
    float *P, *S, *z1sim, *z1cor, *T1, *T2;
    cudaGetSymbolAddress((void**)&feat_sim, g_feat_sim);
    cudaGetSymbolAddress((void**)&feat_cor, g_feat_cor);
    cudaGetSymbolAddress((void**)&rst_sim,  g_rst_sim);
    cudaGetSymbolAddress((void**)&rst_cor,  g_rst_cor);
    cudaGetSymbolAddress((void**)&simB,     g_sim);
    cudaGetSymbolAddress((void**)&corB,     g_cor);
    cudaGetSymbolAddress((void**)&P,        g_P);
    cudaGetSymbolAddress((void**)&S,        g_S);
    cudaGetSymbolAddress((void**)&z1sim,    g_z1sim);
    cudaGetSymbolAddress((void**)&z1cor,    g_z1cor);
    cudaGetSymbolAddress((void**)&T1,       g_T1);
    cudaGetSymbolAddress((void**)&T2,       g_T2);

    float* out = (float*)d_out;
    const int n = N_DST * H;

    // stage 1: per-mode features (merged)
    feat_kernel<<<2 * (N_SRC / 32), 128>>>(x,
        emb0_sim, emb1_sim, W_in_sim, b_in_sim, feat_sim,
        emb0_cor, emb1_cor, W_in_cor, b_in_cor, feat_cor);

    // stage 2: co-attention pooling, both modes (merged)
    attn_kernel<<<2 * N_DST, 256>>>(feat_sim, feat_cor, neigh_sim, neigh_cor,
                                    rst_sim, rst_cor);

    // stage 3: output projections (paired)
    gemm_pair_kernel<<<2 * (N_DST / 32), 128>>>(
        rst_sim, W_out_sim, b_out_sim, simB,
        rst_cor, W_out_cor, b_out_cor, corB);

    // stage 4: mixing
    gemm_pair_kernel<<<2 * (N_DST / 32), 128>>>(
        corB, W_cor2sim, nullptr, P,
        simB, W_sim2cor, nullptr, S);
    combine_z1_kernel<<<n / 256, 256>>>(z1sim, z1cor, simB, corB, P, S, n);
    gemm_pair_kernel<<<2 * (N_DST / 32), 128>>>(
        z1cor, W_cor2sim, nullptr, T1,
        z1sim, W_sim2cor, nullptr, T2);
    combine_final_kernel<<<n / 256, 256>>>(out, simB, corB, P, S, T1, T2, n);
}

// round 5
// speedup vs baseline: 1.3725x; 1.0869x over previous
#include <cuda_runtime.h>

#define N_SRC 65536
#define N_DST 8192
#define MAXN  32
#define H     128

typedef unsigned long long ULL;

// ---------------- f32x2 helpers (Blackwell packed fp32 FMA) ----------------
__device__ __forceinline__ void ffma2(ULL& d, ULL a, ULL b) {
    asm("fma.rn.f32x2 %0, %1, %2, %3;" : "=l"(d) : "l"(a), "l"(b), "l"(d));
}
__device__ __forceinline__ ULL pk2(float x, float y) {
    ULL r; asm("mov.b64 %0, {%1, %2};" : "=l"(r) : "f"(x), "f"(y)); return r;
}
__device__ __forceinline__ float2 upk2(ULL v) {
    float2 f; asm("mov.b64 {%0, %1}, %2;" : "=f"(f.x), "=f"(f.y) : "l"(v)); return f;
}
__device__ __forceinline__ float hsum2(ULL v) { float2 f = upk2(v); return f.x + f.y; }

// ---------------- scratch ----------------
__device__ __align__(16) float g_feat_sim[N_SRC * H];
__device__ __align__(16) float g_feat_cor[N_SRC * H];
__device__ __align__(16) float g_rst_sim[N_DST * H];
__device__ __align__(16) float g_rst_cor[N_DST * H];
__device__ __align__(16) float g_H1[H * H];     // Wos @ Ws2c
__device__ __align__(16) float g_H2[H * H];     // Woc @ Wc2s
__device__ __align__(16) float g_M[256 * 256];  // fused mixing matrix
__device__ __align__(16) float g_c[256];        // fused bias

// ---------------- feat: [emb0[x0]|emb1[x1]] @ W_in + b, both modes ----------------
// 32 rows/CTA, 128 threads; thread j = output column j. x stored TRANSPOSED in
// smem (xb[k][r], 34-pad) so row-pairs are contiguous 8B for packed FFMA2.
__global__ __launch_bounds__(128) void feat_kernel(
    const int* __restrict__ x,
    const float* __restrict__ e0s, const float* __restrict__ e1s,
    const float* __restrict__ Ws,  const float* __restrict__ bs, float* __restrict__ outs,
    const float* __restrict__ e0c, const float* __restrict__ e1c,
    const float* __restrict__ Wc,  const float* __restrict__ bc, float* __restrict__ outc)
{
    __shared__ float xb[H][34];
    const bool is_sim = blockIdx.x < (N_SRC / 32);
    const int  blk    = is_sim ? blockIdx.x : blockIdx.x - (N_SRC / 32);
    const float* emb0 = is_sim ? e0s : e0c;
    const float* emb1 = is_sim ? e1s : e1c;
    const float* W    = is_sim ? Ws  : Wc;
    const float* b    = is_sim ? bs  : bc;
    float*       out  = is_sim ? outs : outc;

    const int base = blk * 32;
    const int tid = threadIdx.x;

    // gather transposed: thread tid owns channel h = tid
    {
        const int h = tid;
        if (h < 32) {
#pragma unroll 4
            for (int r = 0; r < 32; r++)
                xb[h][r] = emb0[x[(base + r) * 2 + 0] * 32 + h];
        } else {
#pragma unroll 4
            for (int r = 0; r < 32; r++)
                xb[h][r] = emb1[x[(base + r) * 2 + 1] * 96 + (h - 32)];
        }
    }
    __syncthreads();

    const int j = tid;
    ULL acc[16];
#pragma unroll
    for (int rp = 0; rp < 16; rp++) acc[rp] = 0ULL;

#pragma unroll 4
    for (int k = 0; k < H; k++) {
        const float wv = W[k * H + j];
        const ULL wd = pk2(wv, wv);
        const ULL* xp = (const ULL*)&xb[k][0];
#pragma unroll
        for (int rp = 0; rp < 16; rp++) ffma2(acc[rp], xp[rp], wd);
    }
    const float bj = b[j];
#pragma unroll
    for (int rp = 0; rp < 16; rp++) {
        const float2 f = upk2(acc[rp]);
        out[(base + 2 * rp + 0) * H + j] = f.x + bj;
        out[(base + 2 * rp + 1) * H + j] = f.y + bj;
    }
}

// ---------------- co-attention pool (collapsed under the mean), both modes ----------------
__global__ __launch_bounds__(256, 5) void attn_kernel(
    const float* __restrict__ feat_sim, const float* __restrict__ feat_cor,
    const int* __restrict__ neigh_sim, const int* __restrict__ neigh_cor,
    float* __restrict__ rst_sim, float* __restrict__ rst_cor)
{
    __shared__ float Ds[32][132];
    __shared__ float Qs[32][132];
    __shared__ float rowpart[8][32];
    __shared__ float wvpart[8][32];
    __shared__ float invcol[32];
    __shared__ float invrow[32];
    __shared__ float wv[32];
    __shared__ float vv[32];
    __shared__ float coef[32];
    __shared__ float O[3 * H];

    const bool is_sim = blockIdx.x < N_DST;
    const int  node   = is_sim ? blockIdx.x : (blockIdx.x - N_DST);
    const float* feat = is_sim ? feat_sim : feat_cor;
    const int* idxD = is_sim ? neigh_cor : neigh_sim;
    const int* idxQ = is_sim ? neigh_sim : neigh_cor;
    float*     rst  = is_sim ? rst_sim : rst_cor;

    const int tid = threadIdx.x;
    const int lane = tid & 31;
    const int w = tid >> 5;

#pragma unroll
    for (int i = 0; i < 4; i++) {
        const int r = w * 4 + i;
        const int id = idxD[node * 32 + r];
        ((float4*)&Ds[r][0])[lane] = ((const float4*)feat)[id * 32 + lane];
        const int iq = idxQ[node * 32 + r];
        ((float4*)&Qs[r][0])[lane] = ((const float4*)feat)[iq * 32 + lane];
    }
    __syncthreads();

    // L[m][k] + exp via packed FFMA2 (even/odd h halves per accumulator)
    float e0, e1, e2, e3;
    {
        const int k0 = w * 4;
        ULL a0 = 0ULL, a1 = 0ULL, a2 = 0ULL, a3 = 0ULL;
        const ulonglong2* dr  = (const ulonglong2*)&Ds[lane][0];
        const ulonglong2* q0r = (const ulonglong2*)&Qs[k0 + 0][0];
        const ulonglong2* q1r = (const ulonglong2*)&Qs[k0 + 1][0];
        const ulonglong2* q2r = (const ulonglong2*)&Qs[k0 + 2][0];
        const ulonglong2* q3r = (const ulonglong2*)&Qs[k0 + 3][0];
#pragma unroll
        for (int h4 = 0; h4 < 32; ++h4) {
            const ulonglong2 d  = dr[h4];
            const ulonglong2 q0 = q0r[h4];
            const ulonglong2 q1 = q1r[h4];
            const ulonglong2 q2 = q2r[h4];
            const ulonglong2 q3 = q3r[h4];
            ffma2(a0, d.x, q0.x); ffma2(a0, d.y, q0.y);
            ffma2(a1, d.x, q1.x); ffma2(a1, d.y, q1.y);
            ffma2(a2, d.x, q2.x); ffma2(a2, d.y, q2.y);
            ffma2(a3, d.x, q3.x); ffma2(a3, d.y, q3.y);
        }
        e0 = __expf(hsum2(a0)); e1 = __expf(hsum2(a1));
        e2 = __expf(hsum2(a2)); e3 = __expf(hsum2(a3));

        rowpart[w][lane] = e0 + e1 + e2 + e3;

        float s0 = e0, s1 = e1, s2 = e2, s3 = e3;
#pragma unroll
        for (int off = 16; off; off >>= 1) {
            s0 += __shfl_xor_sync(0xffffffffu, s0, off);
            s1 += __shfl_xor_sync(0xffffffffu, s1, off);
            s2 += __shfl_xor_sync(0xffffffffu, s2, off);
            s3 += __shfl_xor_sync(0xffffffffu, s3, off);
        }
        if (lane == 0) {
            invcol[k0 + 0] = __frcp_rn(s0);
            invcol[k0 + 1] = __frcp_rn(s1);
            invcol[k0 + 2] = __frcp_rn(s2);
            invcol[k0 + 3] = __frcp_rn(s3);
        }
    }
    __syncthreads();

    if (tid < 32) {
        float s = 0.f;
#pragma unroll
        for (int i = 0; i < 8; i++) s += rowpart[i][tid];
        invrow[tid] = __frcp_rn(s);
    }
    __syncthreads();

    {
        const int k0 = w * 4;
        wvpart[w][lane] = e0 * invcol[k0] + e1 * invcol[k0 + 1]
                        + e2 * invcol[k0 + 2] + e3 * invcol[k0 + 3];
    }
    __syncthreads();
    if (tid < 32) {
        float s = 0.f;
#pragma unroll
        for (int i = 0; i < 8; i++) s += wvpart[i][tid];
        wv[tid]   = s;
        coef[tid] = s * invrow[tid];
    }
    __syncthreads();

    {
        const float cc = coef[lane];
        float s0 = cc * e0, s1 = cc * e1, s2 = cc * e2, s3 = cc * e3;
#pragma unroll
        for (int off = 16; off; off >>= 1) {
            s0 += __shfl_xor_sync(0xffffffffu, s0, off);
            s1 += __shfl_xor_sync(0xffffffffu, s1, off);
            s2 += __shfl_xor_sync(0xffffffffu, s2, off);
            s3 += __shfl_xor_sync(0xffffffffu, s3, off);
        }
        if (lane == 0) {
            const int k0 = w * 4;
            vv[k0 + 0] = s0; vv[k0 + 1] = s1; vv[k0 + 2] = s2; vv[k0 + 3] = s3;
        }
    }
    __syncthreads();

    if (tid < 128) {
        const int h = tid;
        float sq = 0.f, scq = 0.f;
#pragma unroll
        for (int m = 0; m < 32; m++) {
            const float q = Qs[m][h];
            sq  += q;
            scq += vv[m] * q;
        }
        O[h]         = sq;
        O[2 * H + h] = scq;
    } else {
        const int h = tid - 128;
        float sdw = 0.f;
#pragma unroll
        for (int m = 0; m < 32; m++) sdw += wv[m] * Ds[m][h];
        O[H + h] = sdw;
    }
    __syncthreads();

    if (tid < 128) {
        const int h = tid;
        const float r = (O[3 * h] + O[3 * h + 1] + O[3 * h + 2]) * (1.f / 96.f);
        rst[node * H + h] = feat[node * H + h] + r;
    }
}

// ---------------- precompute: H1 = Wos@Ws2c, H2 = Woc@Wc2s ----------------
__global__ __launch_bounds__(128) void pre1_kernel(
    const float* __restrict__ Wos, const float* __restrict__ Ws2c,
    const float* __restrict__ Woc, const float* __restrict__ Wc2s,
    float* __restrict__ H1, float* __restrict__ H2)
{
    const bool first = blockIdx.x < H;
    const int r = first ? blockIdx.x : blockIdx.x - H;
    const float* U = first ? Wos : Woc;
    const float* V = first ? Ws2c : Wc2s;
    float* O = first ? H1 : H2;
    const int j = threadIdx.x;
    float s = 0.f;
#pragma unroll 4
    for (int k = 0; k < H; k++) s += U[r * H + k] * V[k * H + j];
    O[r * H + j] = s;
}

// ---------------- precompute: M quadrants ----------------
// M is 256x256, row = source index (rst_sim rows 0..127, rst_cor 128..255),
// col = output (z2sim 0..127, z2cor 128..255).
//  q0 = 0.34*Wos + 0.165*H1@Wc2s      q1 = 0.495*H1
//  q2 = 0.495*H2                      q3 = 0.34*Woc + 0.165*H2@Ws2c
__global__ __launch_bounds__(128) void pre2_kernel(
    const float* __restrict__ Wos, const float* __restrict__ Woc,
    const float* __restrict__ Ws2c, const float* __restrict__ Wc2s,
    const float* __restrict__ H1, const float* __restrict__ H2,
    float* __restrict__ M)
{
    const int quad = blockIdx.x >> 7;
    const int r = blockIdx.x & 127;
    const int j = threadIdx.x;
    if (quad == 0) {
        float s = 0.f;
#pragma unroll 4
        for (int k = 0; k < H; k++) s += H1[r * H + k] * Wc2s[k * H + j];
        M[r * 256 + j] = 0.34f * Wos[r * H + j] + 0.165f * s;
    } else if (quad == 1) {
        M[r * 256 + 128 + j] = 0.495f * H1[r * H + j];
    } else if (quad == 2) {
        M[(128 + r) * 256 + j] = 0.495f * H2[r * H + j];
    } else {
        float s = 0.f;
#pragma unroll 4
        for (int k = 0; k < H; k++) s += H2[r * H + k] * Ws2c[k * H + j];
        M[(128 + r) * 256 + 128 + j] = 0.34f * Woc[r * H + j] + 0.165f * s;
    }
}

// ---------------- precompute: fused bias c (256) ----------------
__global__ __launch_bounds__(128) void pre3_kernel(
    const float* __restrict__ bos, const float* __restrict__ boc,
    const float* __restrict__ Ws2c, const float* __restrict__ Wc2s,
    float* __restrict__ c)
{
    __shared__ float u[H], v[H];
    const int j = threadIdx.x;
    float su = 0.f, sv = 0.f;
    for (int k = 0; k < H; k++) {
        su += bos[k] * Ws2c[k * H + j];
        sv += boc[k] * Wc2s[k * H + j];
    }
    u[j] = su; v[j] = sv;
    __syncthreads();
    float t1 = 0.f, t2 = 0.f;
    for (int k = 0; k < H; k++) {
        t1 += u[k] * Wc2s[k * H + j];
        t2 += v[k] * Ws2c[k * H + j];
    }
    c[j]       = 0.34f * bos[j] + 0.165f * t1 + 0.495f * v[j];
    c[128 + j] = 0.34f * boc[j] + 0.165f * t2 + 0.495f * u[j];
}

// ---------------- fused final GEMM: [z2sim|z2cor] = [rst_sim|rst_cor] @ M + c ----------------
// 32 rows/CTA, 256 threads; thread j = output column j of M. Packed FFMA2 over row pairs.
__global__ __launch_bounds__(256) void mix_kernel(
    const float* __restrict__ rst_sim, const float* __restrict__ rst_cor,
    const float* __restrict__ M, const float* __restrict__ c,
    float* __restrict__ out)
{
    __shared__ float xb[256][34];
    const int base = blockIdx.x * 32;
    const int tid = threadIdx.x;

    // load transposed: thread tid owns source channel k = tid
    {
        const int k = tid;
        const float* src = (k < 128) ? (rst_sim + (size_t)base * H + k)
                                     : (rst_cor + (size_t)base * H + (k - 128));
#pragma unroll 4
        for (int r = 0; r < 32; r++) xb[k][r] = src[r * H];
    }
    __syncthreads();

    const int j = tid;
    ULL acc[16];
#pragma unroll
    for (int rp = 0; rp < 16; rp++) acc[rp] = 0ULL;

#pragma unroll 4
    for (int k = 0; k < 256; k++) {
        const float wv = M[k * 256 + j];
        const ULL wd = pk2(wv, wv);
        const ULL* xp = (const ULL*)&xb[k][0];
#pragma unroll
        for (int rp = 0; rp < 16; rp++) ffma2(acc[rp], xp[rp], wd);
    }

    const float cj = c[j];
    float* o = (j < 128) ? (out + j) : (out + (size_t)N_DST * H + (j - 128));
#pragma unroll
    for (int rp = 0; rp < 16; rp++) {
        const float2 f = upk2(acc[rp]);
        o[(size_t)(base + 2 * rp + 0) * H] = f.x + cj;
        o[(size_t)(base + 2 * rp + 1) * H] = f.y + cj;
    }
}

// ---------------- launch ----------------
extern "C" void kernel_launch(void* const* d_in, const int* in_sizes, int n_in,
                              void* d_out, int out_size)
{
    const int*   x         = (const int*)d_in[0];
    const int*   neigh_sim = (const int*)d_in[1];
    const int*   neigh_cor = (const int*)d_in[2];
    const float* emb0_sim  = (const float*)d_in[3];
    const float* emb1_sim  = (const float*)d_in[4];
    const float* emb0_cor  = (const float*)d_in[5];
    const float* emb1_cor  = (const float*)d_in[6];
    const float* W_in_sim  = (const float*)d_in[7];
    const float* b_in_sim  = (const float*)d_in[8];
    const float* W_in_cor  = (const float*)d_in[9];
    const float* b_in_cor  = (const float*)d_in[10];
    const float* W_out_sim = (const float*)d_in[11];
    const float* b_out_sim = (const float*)d_in[12];
    const float* W_out_cor = (const float*)d_in[13];
    const float* b_out_cor = (const float*)d_in[14];
    const float* W_sim2cor = (const float*)d_in[15];
    const float* W_cor2sim = (const float*)d_in[16];

    float *feat_sim, *feat_cor, *rst_sim, *rst_cor, *H1, *H2, *M, *c;
    cudaGetSymbolAddress((void**)&feat_sim, g_feat_sim);
    cudaGetSymbolAddress((void**)&feat_cor, g_feat_cor);
    cudaGetSymbolAddress((void**)&rst_sim,  g_rst_sim);
    cudaGetSymbolAddress((void**)&rst_cor,  g_rst_cor);
    cudaGetSymbolAddress((void**)&H1,       g_H1);
    cudaGetSymbolAddress((void**)&H2,       g_H2);
    cudaGetSymbolAddress((void**)&M,        g_M);
    cudaGetSymbolAddress((void**)&c,        g_c);

    float* out = (float*)d_out;

    // weight precompute (independent of feat/attn; tiny)
    pre1_kernel<<<2 * H, 128>>>(W_out_sim, W_sim2cor, W_out_cor, W_cor2sim, H1, H2);
    pre2_kernel<<<4 * H, 128>>>(W_out_sim, W_out_cor, W_sim2cor, W_cor2sim, H1, H2, M);
    pre3_kernel<<<1, 128>>>(b_out_sim, b_out_cor, W_sim2cor, W_cor2sim, c);

    // stage 1: per-mode features
    feat_kernel<<<2 * (N_SRC / 32), 128>>>(x,
        emb0_sim, emb1_sim, W_in_sim, b_in_sim, feat_sim,
        emb0_cor, emb1_cor, W_in_cor, b_in_cor, feat_cor);

    // stage 2: co-attention pooling
    attn_kernel<<<2 * N_DST, 256>>>(feat_sim, feat_cor, neigh_sim, neigh_cor,
                                    rst_sim, rst_cor);

    // stage 3+4 fused: one GEMM against precomputed M, writes d_out directly
    mix_kernel<<<N_DST / 32, 256>>>(rst_sim, rst_cor, M, c, out);
}

// round 6
// speedup vs baseline: 1.7503x; 1.2752x over previous
#include <cuda_runtime.h>
#include <cstdint>

#define N_SRC 65536
#define N_DST 8192
#define MAXN  32
#define H     128

typedef unsigned long long ULL;

// ---------------- f32x2 helpers ----------------
__device__ __forceinline__ void ffma2(ULL& d, ULL a, ULL b) {
    asm("fma.rn.f32x2 %0, %1, %2, %3;" : "=l"(d) : "l"(a), "l"(b), "l"(d));
}
__device__ __forceinline__ ULL pk2(float x, float y) {
    ULL r; asm("mov.b64 %0, {%1, %2};" : "=l"(r) : "f"(x), "f"(y)); return r;
}
__device__ __forceinline__ float2 upk2(ULL v) {
    float2 f; asm("mov.b64 {%0, %1}, %2;" : "=f"(f.x), "=f"(f.y) : "l"(v)); return f;
}

// ---------------- tf32 mma helpers ----------------
__device__ __forceinline__ uint32_t tf32r(float x) {
    uint32_t r; asm("cvt.rna.tf32.f32 %0, %1;" : "=r"(r) : "f"(x)); return r;
}
__device__ __forceinline__ void mma_tf32(float& d0, float& d1, float& d2, float& d3,
    uint32_t a0, uint32_t a1, uint32_t a2, uint32_t a3, uint32_t b0, uint32_t b1)
{
    asm volatile("mma.sync.aligned.m16n8k8.row.col.f32.tf32.tf32.f32 "
        "{%0,%1,%2,%3}, {%4,%5,%6,%7}, {%8,%9}, {%0,%1,%2,%3};"
        : "+f"(d0), "+f"(d1), "+f"(d2), "+f"(d3)
        : "r"(a0), "r"(a1), "r"(a2), "r"(a3), "r"(b0), "r"(b1));
}

// ---------------- scratch ----------------
__device__ __align__(16) float g_feat_sim[N_SRC * H];
__device__ __align__(16) float g_feat_cor[N_SRC * H];
__device__ __align__(16) float g_rst_sim[N_DST * H];
__device__ __align__(16) float g_rst_cor[N_DST * H];
__device__ __align__(16) float g_H1[H * H];
__device__ __align__(16) float g_H2[H * H];
__device__ __align__(16) float g_M[256 * 256];
__device__ __align__(16) float g_c[256];

// ---------------- feat: [emb0[x0]|emb1[x1]] @ W_in + b, both modes ----------------
// 64 rows/CTA, 128 threads. Thread (half=tid>>6, jj=tid&63) computes output
// columns jj and jj+64 for the 16 row-pairs of its half. Per k: 16 LDS.64
// (broadcast) feed 32 FFMA2.
__global__ __launch_bounds__(128) void feat_kernel(
    const int* __restrict__ x,
    const float* __restrict__ e0s, const float* __restrict__ e1s,
    const float* __restrict__ Ws,  const float* __restrict__ bs, float* __restrict__ outs,
    const float* __restrict__ e0c, const float* __restrict__ e1c,
    const float* __restrict__ Wc,  const float* __restrict__ bc, float* __restrict__ outc)
{
    __shared__ float xb[H][66];   // xb[k][r], r = 0..63
    __shared__ int2  xs[64];

    const int halfgrid = N_SRC / 64;
    const bool is_sim = blockIdx.x < halfgrid;
    const int  blk    = is_sim ? blockIdx.x : blockIdx.x - halfgrid;
    const float* emb0 = is_sim ? e0s : e0c;
    const float* emb1 = is_sim ? e1s : e1c;
    const float* W    = is_sim ? Ws  : Wc;
    const float* b    = is_sim ? bs  : bc;
    float*       out  = is_sim ? outs : outc;

    const int base = blk * 64;
    const int tid = threadIdx.x;

    if (tid < 64) xs[tid] = ((const int2*)x)[base + tid];
    __syncthreads();

    // gather transposed: thread owns channel k = tid
    {
        const int k = tid;
        if (k < 32) {
#pragma unroll 8
            for (int r = 0; r < 64; r++)
                xb[k][r] = emb0[xs[r].x * 32 + k];
        } else {
#pragma unroll 8
            for (int r = 0; r < 64; r++)
                xb[k][r] = emb1[xs[r].y * 96 + (k - 32)];
        }
    }
    __syncthreads();

    const int jj = tid & 63;
    const int half = tid >> 6;
    const int j0 = jj, j1 = jj + 64;

    ULL acc0[16], acc1[16];
#pragma unroll
    for (int rp = 0; rp < 16; rp++) { acc0[rp] = 0ULL; acc1[rp] = 0ULL; }

#pragma unroll 2
    for (int k = 0; k < H; k++) {
        const float w0 = W[k * H + j0];
        const float w1 = W[k * H + j1];
        const ULL wd0 = pk2(w0, w0);
        const ULL wd1 = pk2(w1, w1);
        const ULL* xp = (const ULL*)&xb[k][half * 32];
#pragma unroll
        for (int rp = 0; rp < 16; rp++) {
            const ULL xv = xp[rp];
            ffma2(acc0[rp], xv, wd0);
            ffma2(acc1[rp], xv, wd1);
        }
    }
    const float b0 = b[j0], b1 = b[j1];
    const int rbase = base + half * 32;
#pragma unroll
    for (int rp = 0; rp < 16; rp++) {
        const float2 f0 = upk2(acc0[rp]);
        const float2 f1 = upk2(acc1[rp]);
        out[(rbase + 2 * rp + 0) * H + j0] = f0.x + b0;
        out[(rbase + 2 * rp + 1) * H + j0] = f0.y + b0;
        out[(rbase + 2 * rp + 0) * H + j1] = f1.x + b1;
        out[(rbase + 2 * rp + 1) * H + j1] = f1.y + b1;
    }
}

// ---------------- co-attention pool: tf32 MMA for L, collapsed pooling ----------------
// 256 threads per node. 8 warps tile L(32x32) as (mt in {0,1}) x (nt in {0..3}),
// each warp: m16n8k8 over 16 k-chunks. E = exp(L) written once to smem; stats
// are 3 short warp phases; channel sums unchanged.
__global__ __launch_bounds__(256) void attn_kernel(
    const float* __restrict__ feat_sim, const float* __restrict__ feat_cor,
    const int* __restrict__ neigh_sim, const int* __restrict__ neigh_cor,
    float* __restrict__ rst_sim, float* __restrict__ rst_cor)
{
    __shared__ float Ds[32][132];
    __shared__ float Qs[32][132];
    __shared__ float Es[32][33];
    __shared__ float invcol[32];
    __shared__ float invrow[32];
    __shared__ float wv[32];
    __shared__ float vv[32];
    __shared__ float coef[32];
    __shared__ float O[3 * H];

    const bool is_sim = blockIdx.x < N_DST;
    const int  node   = is_sim ? blockIdx.x : (blockIdx.x - N_DST);
    const float* feat = is_sim ? feat_sim : feat_cor;
    const int* idxD = is_sim ? neigh_cor : neigh_sim;   // sim: D=nf_cor
    const int* idxQ = is_sim ? neigh_sim : neigh_cor;
    float*     rst  = is_sim ? rst_sim : rst_cor;

    const int tid = threadIdx.x;
    const int lane = tid & 31;
    const int w = tid >> 5;

    // gather
#pragma unroll
    for (int i = 0; i < 4; i++) {
        const int r = w * 4 + i;
        const int id = idxD[node * 32 + r];
        ((float4*)&Ds[r][0])[lane] = ((const float4*)feat)[id * 32 + lane];
        const int iq = idxQ[node * 32 + r];
        ((float4*)&Qs[r][0])[lane] = ((const float4*)feat)[iq * 32 + lane];
    }
    __syncthreads();

    // ---- L via tf32 MMA, then E = exp(L) ----
    {
        const int mt = w & 1;
        const int nt = w >> 1;
        const int gid = lane >> 2;
        const int tig = lane & 3;
        const int rA0 = mt * 16 + gid;
        const int rA1 = rA0 + 8;
        const int cn  = nt * 8 + gid;     // Q row for B fragment

        float c0 = 0.f, c1 = 0.f, c2 = 0.f, c3 = 0.f;
#pragma unroll
        for (int kc = 0; kc < 16; kc++) {
            const int k0 = kc * 8;
            const uint32_t a0 = tf32r(Ds[rA0][k0 + tig]);
            const uint32_t a1 = tf32r(Ds[rA1][k0 + tig]);
            const uint32_t a2 = tf32r(Ds[rA0][k0 + tig + 4]);
            const uint32_t a3 = tf32r(Ds[rA1][k0 + tig + 4]);
            const uint32_t b0 = tf32r(Qs[cn][k0 + tig]);
            const uint32_t b1 = tf32r(Qs[cn][k0 + tig + 4]);
            mma_tf32(c0, c1, c2, c3, a0, a1, a2, a3, b0, b1);
        }
        const int ec = nt * 8 + 2 * tig;
        Es[rA0][ec]     = __expf(c0);
        Es[rA0][ec + 1] = __expf(c1);
        Es[rA1][ec]     = __expf(c2);
        Es[rA1][ec + 1] = __expf(c3);
    }
    __syncthreads();

    // ---- stats: rowsum (warp 0) / colsum (warp 1) ----
    if (w == 0) {
        const int m = lane;
        float s = 0.f;
#pragma unroll
        for (int k = 0; k < 32; k++) s += Es[m][k];
        invrow[m] = __frcp_rn(s);
    } else if (w == 1) {
        const int k = lane;
        float s = 0.f;
#pragma unroll
        for (int m = 0; m < 32; m++) s += Es[m][k];
        invcol[k] = __frcp_rn(s);
    }
    __syncthreads();

    // wv[m] = sum_k E[m][k]*invcol[k];  coef[m] = wv[m]*invrow[m]
    if (w == 0) {
        const int m = lane;
        float s = 0.f;
#pragma unroll
        for (int k = 0; k < 32; k++) s += Es[m][k] * invcol[k];
        wv[m] = s;
        coef[m] = s * invrow[m];
    }
    __syncthreads();

    // vv[k] = sum_m coef[m]*E[m][k]
    if (w == 1) {
        const int k = lane;
        float s = 0.f;
#pragma unroll
        for (int m = 0; m < 32; m++) s += coef[m] * Es[m][k];
        vv[k] = s;
    }
    __syncthreads();

    // ---- channel reductions ----
    if (tid < 128) {
        const int h = tid;
        float sq = 0.f, scq = 0.f;
#pragma unroll
        for (int m = 0; m < 32; m++) {
            const float q = Qs[m][h];
            sq  += q;
            scq += vv[m] * q;
        }
        O[h]         = sq;
        O[2 * H + h] = scq;
    } else {
        const int h = tid - 128;
        float sdw = 0.f;
#pragma unroll
        for (int m = 0; m < 32; m++) sdw += wv[m] * Ds[m][h];
        O[H + h] = sdw;
    }
    __syncthreads();

    if (tid < 128) {
        const int h = tid;
        const float r = (O[3 * h] + O[3 * h + 1] + O[3 * h + 2]) * (1.f / 96.f);
        rst[node * H + h] = feat[node * H + h] + r;
    }
}

// ---------------- precompute: H1 = Wos@Ws2c, H2 = Woc@Wc2s ----------------
__global__ __launch_bounds__(128) void pre1_kernel(
    const float* __restrict__ Wos, const float* __restrict__ Ws2c,
    const float* __restrict__ Woc, const float* __restrict__ Wc2s,
    float* __restrict__ H1, float* __restrict__ H2)
{
    const bool first = blockIdx.x < H;
    const int r = first ? blockIdx.x : blockIdx.x - H;
    const float* U = first ? Wos : Woc;
    const float* V = first ? Ws2c : Wc2s;
    float* Oo = first ? H1 : H2;
    const int j = threadIdx.x;
    float s = 0.f;
#pragma unroll 4
    for (int k = 0; k < H; k++) s += U[r * H + k] * V[k * H + j];
    Oo[r * H + j] = s;
}

// ---------------- precompute: M quadrants ----------------
__global__ __launch_bounds__(128) void pre2_kernel(
    const float* __restrict__ Wos, const float* __restrict__ Woc,
    const float* __restrict__ Ws2c, const float* __restrict__ Wc2s,
    const float* __restrict__ H1, const float* __restrict__ H2,
    float* __restrict__ M)
{
    const int quad = blockIdx.x >> 7;
    const int r = blockIdx.x & 127;
    const int j = threadIdx.x;
    if (quad == 0) {
        float s = 0.f;
#pragma unroll 4
        for (int k = 0; k < H; k++) s += H1[r * H + k] * Wc2s[k * H + j];
        M[r * 256 + j] = 0.34f * Wos[r * H + j] + 0.165f * s;
    } else if (quad == 1) {
        M[r * 256 + 128 + j] = 0.495f * H1[r * H + j];
    } else if (quad == 2) {
        M[(128 + r) * 256 + j] = 0.495f * H2[r * H + j];
    } else {
        float s = 0.f;
#pragma unroll 4
        for (int k = 0; k < H; k++) s += H2[r * H + k] * Ws2c[k * H + j];
        M[(128 + r) * 256 + 128 + j] = 0.34f * Woc[r * H + j] + 0.165f * s;
    }
}

// ---------------- precompute: fused bias c ----------------
__global__ __launch_bounds__(128) void pre3_kernel(
    const float* __restrict__ bos, const float* __restrict__ boc,
    const float* __restrict__ Ws2c, const float* __restrict__ Wc2s,
    float* __restrict__ c)
{
    __shared__ float u[H], v[H];
    const int j = threadIdx.x;
    float su = 0.f, sv = 0.f;
    for (int k = 0; k < H; k++) {
        su += bos[k] * Ws2c[k * H + j];
        sv += boc[k] * Wc2s[k * H + j];
    }
    u[j] = su; v[j] = sv;
    __syncthreads();
    float t1 = 0.f, t2 = 0.f;
    for (int k = 0; k < H; k++) {
        t1 += u[k] * Wc2s[k * H + j];
        t2 += v[k] * Ws2c[k * H + j];
    }
    c[j]       = 0.34f * bos[j] + 0.165f * t1 + 0.495f * v[j];
    c[128 + j] = 0.34f * boc[j] + 0.165f * t2 + 0.495f * u[j];
}

// ---------------- fused final GEMM: [z2sim|z2cor] = [rst_sim|rst_cor] @ M + c ----------------
// 32 rows/CTA, 128 threads; thread jj owns cols jj and jj+128 (1:2 LDS:FFMA2).
__global__ __launch_bounds__(128) void mix_kernel(
    const float* __restrict__ rst_sim, const float* __restrict__ rst_cor,
    const float* __restrict__ M, const float* __restrict__ c,
    float* __restrict__ out)
{
    __shared__ float xb[256][34];
    const int base = blockIdx.x * 32;
    const int tid = threadIdx.x;

    for (int kk = tid; kk < 256; kk += 128) {
        const float* src = (kk < 128) ? (rst_sim + (size_t)base * H + kk)
                                      : (rst_cor + (size_t)base * H + (kk - 128));
#pragma unroll 4
        for (int r = 0; r < 32; r++) xb[kk][r] = src[r * H];
    }
    __syncthreads();

    const int j0 = tid;          // z2sim column
    const int j1 = tid + 128;    // z2cor column
    ULL acc0[16], acc1[16];
#pragma unroll
    for (int rp = 0; rp < 16; rp++) { acc0[rp] = 0ULL; acc1[rp] = 0ULL; }

#pragma unroll 2
    for (int k = 0; k < 256; k++) {
        const float w0 = M[k * 256 + j0];
        const float w1 = M[k * 256 + j1];
        const ULL wd0 = pk2(w0, w0);
        const ULL wd1 = pk2(w1, w1);
        const ULL* xp = (const ULL*)&xb[k][0];
#pragma unroll
        for (int rp = 0; rp < 16; rp++) {
            const ULL xv = xp[rp];
            ffma2(acc0[rp], xv, wd0);
            ffma2(acc1[rp], xv, wd1);
        }
    }

    const float c0 = c[j0], c1 = c[j1];
    float* o0 = out + j0;
    float* o1 = out + (size_t)N_DST * H + tid;
#pragma unroll
    for (int rp = 0; rp < 16; rp++) {
        const float2 f0 = upk2(acc0[rp]);
        const float2 f1 = upk2(acc1[rp]);
        o0[(size_t)(base + 2 * rp + 0) * H] = f0.x + c0;
        o0[(size_t)(base + 2 * rp + 1) * H] = f0.y + c0;
        o1[(size_t)(base + 2 * rp + 0) * H] = f1.x + c1;
        o1[(size_t)(base + 2 * rp + 1) * H] = f1.y + c1;
    }
}

// ---------------- launch ----------------
extern "C" void kernel_launch(void* const* d_in, const int* in_sizes, int n_in,
                              void* d_out, int out_size)
{
    const int*   x         = (const int*)d_in[0];
    const int*   neigh_sim = (const int*)d_in[1];
    const int*   neigh_cor = (const int*)d_in[2];
    const float* emb0_sim  = (const float*)d_in[3];
    const float* emb1_sim  = (const float*)d_in[4];
    const float* emb0_cor  = (const float*)d_in[5];
    const float* emb1_cor  = (const float*)d_in[6];
    const float* W_in_sim  = (const float*)d_in[7];
    const float* b_in_sim  = (const float*)d_in[8];
    const float* W_in_cor  = (const float*)d_in[9];
    const float* b_in_cor  = (const float*)d_in[10];
    const float* W_out_sim = (const float*)d_in[11];
    const float* b_out_sim = (const float*)d_in[12];
    const float* W_out_cor = (const float*)d_in[13];
    const float* b_out_cor = (const float*)d_in[14];
    const float* W_sim2cor = (const float*)d_in[15];
    const float* W_cor2sim = (const float*)d_in[16];

    float *feat_sim, *feat_cor, *rst_sim, *rst_cor, *H1, *H2, *M, *c;
    cudaGetSymbolAddress((void**)&feat_sim, g_feat_sim);
    cudaGetSymbolAddress((void**)&feat_cor, g_feat_cor);
    cudaGetSymbolAddress((void**)&rst_sim,  g_rst_sim);
    cudaGetSymbolAddress((void**)&rst_cor,  g_rst_cor);
    cudaGetSymbolAddress((void**)&H1,       g_H1);
    cudaGetSymbolAddress((void**)&H2,       g_H2);
    cudaGetSymbolAddress((void**)&M,        g_M);
    cudaGetSymbolAddress((void**)&c,        g_c);

    float* out = (float*)d_out;

    pre1_kernel<<<2 * H, 128>>>(W_out_sim, W_sim2cor, W_out_cor, W_cor2sim, H1, H2);
    pre2_kernel<<<4 * H, 128>>>(W_out_sim, W_out_cor, W_sim2cor, W_cor2sim, H1, H2, M);
    pre3_kernel<<<1, 128>>>(b_out_sim, b_out_cor, W_sim2cor, W_cor2sim, c);

    feat_kernel<<<2 * (N_SRC / 64), 128>>>(x,
        emb0_sim, emb1_sim, W_in_sim, b_in_sim, feat_sim,
        emb0_cor, emb1_cor, W_in_cor, b_in_cor, feat_cor);

    attn_kernel<<<2 * N_DST, 256>>>(feat_sim, feat_cor, neigh_sim, neigh_cor,
                                    rst_sim, rst_cor);

    mix_kernel<<<N_DST / 32, 128>>>(rst_sim, rst_cor, M, c, out);
}